// round 7
// baseline (speedup 1.0000x reference)
#include <cuda_runtime.h>
#include <stdint.h>

// out[i,j] = 2*x[i,j] + 5 - (i+j), x: [8192, 8192] fp32.
// Flat-grid HBM-streaming kernel at the measured roofline (~6.46 TB/s,
// 80.8% of spec). 4x front-batched float4 loads per thread (MLP=4, measured
// optimum), 512-thread blocks (32KB contiguous per-CTA extent), __ldcs
// evict-first reads, __stwt write-through stores (probe: avoid L2 dirty-line
// residency on the pure write stream).

#define N_DIM 8192
#define M_DIM 8192
#define VEC_PER_ROW_LOG2 11             // 8192/4 = 2048 float4 per row
#define VEC_PER_ROW (1 << VEC_PER_ROW_LOG2)
#define UNROLL 4
#define THREADS 512

__global__ __launch_bounds__(THREADS) void fused_affine_outer_kernel(
    const float4* __restrict__ x, float4* __restrict__ out)
{
    unsigned int base = blockIdx.x * (THREADS * UNROLL) + threadIdx.x;

    float4 in[UNROLL];
#pragma unroll
    for (int k = 0; k < UNROLL; k++) {
        in[k] = __ldcs(&x[base + k * THREADS]);
    }

#pragma unroll
    for (int k = 0; k < UNROLL; k++) {
        unsigned int v  = base + k * THREADS;
        unsigned int i  = v >> VEC_PER_ROW_LOG2;          // row
        unsigned int j4 = (v & (VEC_PER_ROW - 1)) << 2;   // col of lane 0
        float b = 5.0f - (float)(i + j4);

        float4 o;
        o.x = fmaf(in[k].x, 2.0f, b);
        o.y = fmaf(in[k].y, 2.0f, b - 1.0f);
        o.z = fmaf(in[k].z, 2.0f, b - 2.0f);
        o.w = fmaf(in[k].w, 2.0f, b - 3.0f);
        __stwt(&out[v], o);
    }
}

extern "C" void kernel_launch(void* const* d_in, const int* in_sizes, int n_in,
                              void* d_out, int out_size)
{
    const float4* x = (const float4*)d_in[0];
    float4* out = (float4*)d_out;

    const unsigned int total_vec = (N_DIM * M_DIM) / 4;         // 16,777,216
    const unsigned int blocks = total_vec / (THREADS * UNROLL); // 8,192

    fused_affine_outer_kernel<<<blocks, THREADS>>>(x, out);
}

// round 8
// speedup vs baseline: 1.0097x; 1.0097x over previous
#include <cuda_runtime.h>
#include <stdint.h>

// out[i,j] = 2*x[i,j] + 5 - (i+j), x: [8192, 8192] fp32.
//
// FINAL: flat-grid HBM-streaming kernel at the measured machine ceiling
// (~6.46 TB/s, 80.8% of 8 TB/s spec; DRAM pipe ~81.5% busy, all compute
// pipes <6%). Measured design space:
//   UNROLL:   1 -> 82.2us, 4 -> 81.8-82.1us (best), 8 -> 82.6us (occ drop)
//   threads:  256 ~= 512 (512 marginally best)
//   schedule: flat grid beats persistent grid-stride by 10us (per-CTA loop
//             serializes next loads behind prior stores; flat grid keeps
//             fresh front-batched loads in flight via GigaThread)
//   stores:   __stcs beats __stwt by ~1us (L2 write-combining)
// Config: 512 threads, 4x front-batched float4 loads (MLP=4), __ldcs/__stcs
// evict-first hints (zero reuse), exact-cover 8192-block grid.

#define N_DIM 8192
#define M_DIM 8192
#define VEC_PER_ROW_LOG2 11             // 8192/4 = 2048 float4 per row
#define VEC_PER_ROW (1 << VEC_PER_ROW_LOG2)
#define UNROLL 4
#define THREADS 512

__global__ __launch_bounds__(THREADS) void fused_affine_outer_kernel(
    const float4* __restrict__ x, float4* __restrict__ out)
{
    // Each block owns a contiguous chunk of UNROLL*THREADS vectors;
    // within each unroll step the warp's accesses are fully coalesced.
    unsigned int base = blockIdx.x * (THREADS * UNROLL) + threadIdx.x;

    float4 in[UNROLL];
#pragma unroll
    for (int k = 0; k < UNROLL; k++) {
        in[k] = __ldcs(&x[base + k * THREADS]);
    }

#pragma unroll
    for (int k = 0; k < UNROLL; k++) {
        unsigned int v  = base + k * THREADS;
        unsigned int i  = v >> VEC_PER_ROW_LOG2;          // row
        unsigned int j4 = (v & (VEC_PER_ROW - 1)) << 2;   // col of lane 0
        float b = 5.0f - (float)(i + j4);

        float4 o;
        o.x = fmaf(in[k].x, 2.0f, b);
        o.y = fmaf(in[k].y, 2.0f, b - 1.0f);
        o.z = fmaf(in[k].z, 2.0f, b - 2.0f);
        o.w = fmaf(in[k].w, 2.0f, b - 3.0f);
        __stcs(&out[v], o);
    }
}

extern "C" void kernel_launch(void* const* d_in, const int* in_sizes, int n_in,
                              void* d_out, int out_size)
{
    const float4* x = (const float4*)d_in[0];
    float4* out = (float4*)d_out;

    const unsigned int total_vec = (N_DIM * M_DIM) / 4;         // 16,777,216
    const unsigned int blocks = total_vec / (THREADS * UNROLL); // 8,192

    fused_affine_outer_kernel<<<blocks, THREADS>>>(x, out);
}

// round 9
// speedup vs baseline: 1.0113x; 1.0016x over previous
#include <cuda_runtime.h>
#include <stdint.h>

// out[i,j] = 2*x[i,j] + 5 - (i+j), x: [8192, 8192] fp32.
//
// Flat-grid HBM-streaming kernel at the measured machine ceiling
// (~6.46 TB/s, 80.8% of 8 TB/s spec; all compute pipes <6%).
// Design space measured: UNROLL {1,4,8} -> 4 best; threads {256,512} -> 512;
// flat grid >> persistent (+10us); __stcs > __stwt (+1us).
// This round: __ldcg loads (L1 bypass, L2-only) — zero-reuse stream gains
// nothing from L1 allocation; trims l1tex wavefront work per load.

#define N_DIM 8192
#define M_DIM 8192
#define VEC_PER_ROW_LOG2 11             // 8192/4 = 2048 float4 per row
#define VEC_PER_ROW (1 << VEC_PER_ROW_LOG2)
#define UNROLL 4
#define THREADS 512

__global__ __launch_bounds__(THREADS) void fused_affine_outer_kernel(
    const float4* __restrict__ x, float4* __restrict__ out)
{
    // Each block owns a contiguous chunk of UNROLL*THREADS vectors;
    // within each unroll step the warp's accesses are fully coalesced.
    unsigned int base = blockIdx.x * (THREADS * UNROLL) + threadIdx.x;

    float4 in[UNROLL];
#pragma unroll
    for (int k = 0; k < UNROLL; k++) {
        in[k] = __ldcg(&x[base + k * THREADS]);   // L1-bypass load
    }

#pragma unroll
    for (int k = 0; k < UNROLL; k++) {
        unsigned int v  = base + k * THREADS;
        unsigned int i  = v >> VEC_PER_ROW_LOG2;          // row
        unsigned int j4 = (v & (VEC_PER_ROW - 1)) << 2;   // col of lane 0
        float b = 5.0f - (float)(i + j4);

        float4 o;
        o.x = fmaf(in[k].x, 2.0f, b);
        o.y = fmaf(in[k].y, 2.0f, b - 1.0f);
        o.z = fmaf(in[k].z, 2.0f, b - 2.0f);
        o.w = fmaf(in[k].w, 2.0f, b - 3.0f);
        __stcs(&out[v], o);
    }
}

extern "C" void kernel_launch(void* const* d_in, const int* in_sizes, int n_in,
                              void* d_out, int out_size)
{
    const float4* x = (const float4*)d_in[0];
    float4* out = (float4*)d_out;

    const unsigned int total_vec = (N_DIM * M_DIM) / 4;         // 16,777,216
    const unsigned int blocks = total_vec / (THREADS * UNROLL); // 8,192

    fused_affine_outer_kernel<<<blocks, THREADS>>>(x, out);
}

// round 10
// speedup vs baseline: 1.0149x; 1.0035x over previous
#include <cuda_runtime.h>
#include <stdint.h>

// out[i,j] = 2*x[i,j] + 5 - (i+j), x: [8192, 8192] fp32.
//
// FINAL KERNEL — flat-grid HBM-streaming at the measured machine ceiling:
// ~6.46 TB/s (80.8% of 8 TB/s spec), DRAM pipe ~81.5% busy, compute <6%.
//
// Exhausted design space (9 benched rounds, all passing, rel_err 1.3e-9):
//   UNROLL:    1 -> 82.2us | 4 -> 81.8us (BEST) | 8 -> 82.6us (occ 78->61%)
//   threads:   256 -> 82.0us | 512 -> 81.8us (BEST)
//   schedule:  flat grid (BEST) | persistent 1-wave grid-stride -> 92.9us
//              (per-CTA loop serializes next loads behind prior stores;
//               flat grid keeps fresh front-batched loads in flight)
//   loads:     __ldcs 81.8us (BEST) | __ldcg neutral (l1tex not binding)
//   stores:    __stcs (BEST) | __stwt -> 82.9us (loses L2 write-combining)
// Traffic is minimal (1R+1W per element, fully-coalesced 128B); TMA/smem
// staging cannot beat direct LDG/STG (B300 LTS-cap path independence).
//
// Config: 512 threads, 4x front-batched float4 loads per thread (MLP=4),
// __ldcs/__stcs evict-first hints (zero reuse), exact-cover 8192-block grid.

#define N_DIM 8192
#define M_DIM 8192
#define VEC_PER_ROW_LOG2 11             // 8192/4 = 2048 float4 per row
#define VEC_PER_ROW (1 << VEC_PER_ROW_LOG2)
#define UNROLL 4
#define THREADS 512

__global__ __launch_bounds__(THREADS) void fused_affine_outer_kernel(
    const float4* __restrict__ x, float4* __restrict__ out)
{
    // Each block owns a contiguous chunk of UNROLL*THREADS vectors;
    // within each unroll step the warp's accesses are fully coalesced.
    unsigned int base = blockIdx.x * (THREADS * UNROLL) + threadIdx.x;

    float4 in[UNROLL];
#pragma unroll
    for (int k = 0; k < UNROLL; k++) {
        in[k] = __ldcs(&x[base + k * THREADS]);
    }

#pragma unroll
    for (int k = 0; k < UNROLL; k++) {
        unsigned int v  = base + k * THREADS;
        unsigned int i  = v >> VEC_PER_ROW_LOG2;          // row
        unsigned int j4 = (v & (VEC_PER_ROW - 1)) << 2;   // col of lane 0
        float b = 5.0f - (float)(i + j4);

        float4 o;
        o.x = fmaf(in[k].x, 2.0f, b);
        o.y = fmaf(in[k].y, 2.0f, b - 1.0f);
        o.z = fmaf(in[k].z, 2.0f, b - 2.0f);
        o.w = fmaf(in[k].w, 2.0f, b - 3.0f);
        __stcs(&out[v], o);
    }
}

extern "C" void kernel_launch(void* const* d_in, const int* in_sizes, int n_in,
                              void* d_out, int out_size)
{
    const float4* x = (const float4*)d_in[0];
    float4* out = (float4*)d_out;

    const unsigned int total_vec = (N_DIM * M_DIM) / 4;         // 16,777,216
    const unsigned int blocks = total_vec / (THREADS * UNROLL); // 8,192

    fused_affine_outer_kernel<<<blocks, THREADS>>>(x, out);
}